// round 12
// baseline (speedup 1.0000x reference)
#include <cuda_runtime.h>

// Problem constants (z: (4,64,16,32,32) f32, emb: (1024,64) f32)
#define NBATCH 4
#define NC     64
#define SP     16384
#define NROWS  (NBATCH * SP)        // 65536
#define KCODES 1024
#define NZQ    (NBATCH * NC * SP)   // 4194304
#define EP     68                   // padded emb row stride (floats), bank-safe
#define TKC    64                   // codes per smem tile
#define NTIL   (KCODES / TKC)       // 16
#define TILE_CHUNKS ((TKC * EP * 4) / 16)   // 1088 x 16B
#define NBLK_EPI (NROWS / 128)      // 512
#define FB_WARPS 1024

__device__ float    g_embp[KCODES * EP];   // tf32-rounded, padded codebook
__device__ float    g_e2[KCODES];          // frozen code norms
__device__ float    g_z2[NROWS];           // frozen row norms
__device__ float    g_R[NROWS];            // sum |z| per row (for tau)
__device__ unsigned g_maxe_bits;           // bits of max|emb|
__device__ int2     g_cand[NROWS];         // x=i1; y: -2 fb, -1 single, else i2
__device__ int      g_fb[NROWS];
__device__ int      g_fbbk[NROWS];
__device__ unsigned g_fb_cnt = 0;
__device__ double   g_partial[NBLK_EPI];

// ---------------------------------------------------------------------------
__device__ __forceinline__ void cp_async16(unsigned smem_addr, const void* gptr) {
    asm volatile("cp.async.cg.shared.global [%0], [%1], 16;\n"
                 :: "r"(smem_addr), "l"(gptr));
}
__device__ __forceinline__ void cp_commit() {
    asm volatile("cp.async.commit_group;\n");
}
template <int N>
__device__ __forceinline__ void cp_wait() {
    asm volatile("cp.async.wait_group %0;\n" :: "n"(N));
}

#define FMA2(acc, x, y) \
    asm("fma.rn.f32x2 %0, %1, %2, %0;" : "+l"(acc) : "l"(x), "l"(y))
#define ADD2(a, b) \
    asm("add.rn.f32x2 %0, %0, %1;" : "+l"(a) : "l"(b))

// Frozen row load: pairwise z2 tree + packed f32x2 (IDENTICAL to round-1)
__device__ __forceinline__ float load_row_frozen(const float* __restrict__ zp,
                                                 unsigned long long* zr) {
    float zv[NC];
#pragma unroll
    for (int c = 0; c < NC; c++) zv[c] = zp[(size_t)c * SP];
    float t32[32];
#pragma unroll
    for (int i = 0; i < 32; i++)
        t32[i] = __fadd_rn(__fmul_rn(zv[2 * i], zv[2 * i]),
                           __fmul_rn(zv[2 * i + 1], zv[2 * i + 1]));
#pragma unroll
    for (int st = 16; st >= 1; st >>= 1)
#pragma unroll
        for (int i = 0; i < 16; i++)
            if (i < st) t32[i] = __fadd_rn(t32[i], t32[i + st]);
#pragma unroll
    for (int j = 0; j < NC / 2; j++)
        asm("mov.b64 %0, {%1, %2};" : "=l"(zr[j]) : "f"(zv[2 * j]), "f"(zv[2 * j + 1]));
    return t32[0];
}

// Frozen exact score (IDENTICAL chain to rounds 7-9)
__device__ __forceinline__ float frozen_score(const unsigned long long* zr, float z2,
                                              const float* __restrict__ emb, int code) {
    const ulonglong2* ep = (const ulonglong2*)(emb + (size_t)code * NC);
    unsigned long long a0 = 0ull, a1 = 0ull, a2 = 0ull, a3 = 0ull;
#pragma unroll
    for (int i = 0; i < 8; i++) {
        ulonglong2 e01 = ep[2 * i];
        ulonglong2 e23 = ep[2 * i + 1];
        FMA2(a0, zr[4 * i + 0], e01.x);
        FMA2(a1, zr[4 * i + 1], e01.y);
        FMA2(a2, zr[4 * i + 2], e23.x);
        FMA2(a3, zr[4 * i + 3], e23.y);
    }
    ADD2(a0, a1); ADD2(a2, a3); ADD2(a0, a2);
    float lo, hi;
    asm("mov.b64 {%0, %1}, %2;" : "=f"(lo), "=f"(hi) : "l"(a0));
    const float dot = __fadd_rn(lo, hi);
    return __fmaf_rn(dot, -2.0f, __fadd_rn(z2, g_e2[code]));
}

// ---------------------------------------------------------------------------
// Kernel 1: frozen e2, tf32-rounded padded codebook, max|e|
// ---------------------------------------------------------------------------
__global__ void prep_kernel(const float* __restrict__ emb) {
    int k = blockIdx.x * blockDim.x + threadIdx.x;
    if (k < KCODES) {
        const float4* e = (const float4*)(emb + k * NC);
        float s = 0.f, mx = 0.f;
#pragma unroll
        for (int i = 0; i < NC / 4; i++) {
            float4 v = e[i];
            s += v.x * v.x + v.y * v.y + v.z * v.z + v.w * v.w;
            mx = fmaxf(mx, fmaxf(fmaxf(fabsf(v.x), fabsf(v.y)),
                                 fmaxf(fabsf(v.z), fabsf(v.w))));
            unsigned t0, t1, t2, t3;
            asm("cvt.rna.tf32.f32 %0, %1;" : "=r"(t0) : "f"(v.x));
            asm("cvt.rna.tf32.f32 %0, %1;" : "=r"(t1) : "f"(v.y));
            asm("cvt.rna.tf32.f32 %0, %1;" : "=r"(t2) : "f"(v.z));
            asm("cvt.rna.tf32.f32 %0, %1;" : "=r"(t3) : "f"(v.w));
            g_embp[k * EP + 4 * i + 0] = __uint_as_float(t0);
            g_embp[k * EP + 4 * i + 1] = __uint_as_float(t1);
            g_embp[k * EP + 4 * i + 2] = __uint_as_float(t2);
            g_embp[k * EP + 4 * i + 3] = __uint_as_float(t3);
        }
        g_e2[k] = s;
        atomicMax(&g_maxe_bits, __float_as_uint(mx));   // nonneg: bit-cmp == val-cmp
    }
}

// ---------------------------------------------------------------------------
// Kernel 2: frozen z2 + R per row
// ---------------------------------------------------------------------------
__global__ void __launch_bounds__(128) z2r_kernel(const float* __restrict__ z) {
    const int row = blockIdx.x * 128 + threadIdx.x;
    const float* zp = z + (size_t)(row >> 14) * NC * SP + (row & (SP - 1));
    float zv[NC];
#pragma unroll
    for (int c = 0; c < NC; c++) zv[c] = zp[(size_t)c * SP];
    float t32[32];
#pragma unroll
    for (int i = 0; i < 32; i++)
        t32[i] = __fadd_rn(__fmul_rn(zv[2 * i], zv[2 * i]),
                           __fmul_rn(zv[2 * i + 1], zv[2 * i + 1]));
#pragma unroll
    for (int st = 16; st >= 1; st >>= 1)
#pragma unroll
        for (int i = 0; i < 16; i++)
            if (i < st) t32[i] = __fadd_rn(t32[i], t32[i + st]);
    float R = 0.f;
#pragma unroll
    for (int c = 0; c < NC; c++) R += fabsf(zv[c]);
    g_z2[row] = t32[0];
    g_R[row] = R;
}

// ---------------------------------------------------------------------------
// top-3 helpers
// ---------------------------------------------------------------------------
__device__ __forceinline__ void top3_update(float s, int idx, float& s1, int& i1,
                                            float& s2, int& i2, float& s3) {
    if (s < s3) {
        if (s < s2) {
            s3 = s2;
            if (s < s1) { s2 = s1; i2 = i1; s1 = s; i1 = idx; }
            else        { s2 = s;  i2 = idx; }
        } else s3 = s;
    }
}

__device__ __forceinline__ void top3_merge(int m, float& s1, int& i1,
                                           float& s2, int& i2, float& s3) {
    float b1 = __shfl_xor_sync(0xffffffffu, s1, m);
    float b2 = __shfl_xor_sync(0xffffffffu, s2, m);
    float b3 = __shfl_xor_sync(0xffffffffu, s3, m);
    int  j1 = __shfl_xor_sync(0xffffffffu, i1, m);
    int  j2 = __shfl_xor_sync(0xffffffffu, i2, m);
    float n1, n2, n3; int k1, k2;
    if (s1 <= b1) {
        n1 = s1; k1 = i1;
        if (s2 <= b1) { n2 = s2; k2 = i2; n3 = fminf(s3, b1); }
        else          { n2 = b1; k2 = j1; n3 = fminf(s2, b2); }
    } else {
        n1 = b1; k1 = j1;
        if (b2 <= s1) { n2 = b2; k2 = j2; n3 = fminf(b3, s1); }
        else          { n2 = s1; k2 = i1; n3 = fminf(b2, s2); }
    }
    s1 = n1; i1 = k1; s2 = n2; i2 = k2; s3 = n3;
}

__device__ __forceinline__ void emit_row(int row, float s1, int i1, float s2,
                                         int i2, float s3, float tau) {
    int y;
    if (s3 <= s1 + tau) {
        y = -2;
        unsigned p = atomicAdd(&g_fb_cnt, 1u);
        g_fb[p] = row;
    } else if (s2 <= s1 + tau) y = i2;
    else y = -1;
    g_cand[row] = make_int2(i1, y);
}

// ---------------------------------------------------------------------------
// Kernel 3: tensor sweep — tf32 m16n8k8 mma filter; per-row top-3 approx.
// Block = 128 thr (4 warps), 64 rows; codebook streamed in 64-code tiles.
// ---------------------------------------------------------------------------
__global__ void __launch_bounds__(128) sweep_kernel(const float* __restrict__ z) {
    __shared__ __align__(16) float se[2][TKC * EP];   // 2 x 17.0 KB
    __shared__ __align__(16) float se2[2][TKC];

    const int tid = threadIdx.x;
    const int warp = tid >> 5;
    const int lane = tid & 31;
    const int grp = lane >> 2;     // 0..7 : D-row group
    const int qd = lane & 3;       // 0..3 : k/col subgroup

    const int blockRow = blockIdx.x * 64;

    // Prime tiles 0,1
#pragma unroll
    for (int t = 0; t < 2; t++) {
        unsigned sb = (unsigned)__cvta_generic_to_shared(&se[t][0]);
        const char* gb = (const char*)(g_embp + (size_t)t * TKC * EP);
        for (int j = tid; j < TILE_CHUNKS; j += 128)
            cp_async16(sb + j * 16, gb + j * 16);
        if (tid < 16)
            cp_async16((unsigned)__cvta_generic_to_shared(&se2[t][tid * 4]),
                       (const char*)(g_e2 + t * TKC) + tid * 16);
        cp_commit();
    }

    // A fragments: rows rowA (d0/d1) and rowB=rowA+8 (d2/d3)
    const int bB = blockRow >> 14;
    const float* zbase = z + (size_t)bB * NC * SP;
    const int sA = (blockRow & (SP - 1)) + warp * 16 + grp;
    const int sB = sA + 8;
    const int rowA = blockRow + warp * 16 + grp;
    const int rowB = rowA + 8;

    unsigned a[32];
#pragma unroll
    for (int j = 0; j < 8; j++) {
        float xA0 = zbase[(size_t)(qd + 8 * j) * SP + sA];
        float xB0 = zbase[(size_t)(qd + 8 * j) * SP + sB];
        float xA1 = zbase[(size_t)(qd + 4 + 8 * j) * SP + sA];
        float xB1 = zbase[(size_t)(qd + 4 + 8 * j) * SP + sB];
        asm("cvt.rna.tf32.f32 %0, %1;" : "=r"(a[4 * j + 0]) : "f"(xA0));
        asm("cvt.rna.tf32.f32 %0, %1;" : "=r"(a[4 * j + 1]) : "f"(xB0));
        asm("cvt.rna.tf32.f32 %0, %1;" : "=r"(a[4 * j + 2]) : "f"(xA1));
        asm("cvt.rna.tf32.f32 %0, %1;" : "=r"(a[4 * j + 3]) : "f"(xB1));
    }

    const float maxe = __uint_as_float(g_maxe_bits);
    const float z2A = g_z2[rowA], z2B = g_z2[rowB];
    const float tauA = __fmaf_rn(g_R[rowA] * maxe, 0.0078125f, 3e-4f);
    const float tauB = __fmaf_rn(g_R[rowB] * maxe, 0.0078125f, 3e-4f);

    const float INF = __int_as_float(0x7f800000);
    float s1A = INF, s2A = INF, s3A = INF; int i1A = 0, i2A = 0;
    float s1B = INF, s2B = INF, s3B = INF; int i1B = 0, i2B = 0;

    for (int t = 0; t < NTIL; t++) {
        if (t < NTIL - 1) cp_wait<1>(); else cp_wait<0>();
        __syncthreads();
        const int buf = t & 1;
        const int kt = t * TKC;

#pragma unroll 2
        for (int c = 0; c < 8; c++) {
            float d0 = 0.f, d1 = 0.f, d2 = 0.f, d3 = 0.f;
            const float* bt = &se[buf][(8 * c + grp) * EP + qd];
#pragma unroll
            for (int j = 0; j < 8; j++) {
                unsigned b0 = __float_as_uint(bt[8 * j]);
                unsigned b1 = __float_as_uint(bt[8 * j + 4]);
                asm("mma.sync.aligned.m16n8k8.row.col.f32.tf32.tf32.f32 "
                    "{%0,%1,%2,%3}, {%4,%5,%6,%7}, {%8,%9}, {%0,%1,%2,%3};"
                    : "+f"(d0), "+f"(d1), "+f"(d2), "+f"(d3)
                    : "r"(a[4 * j]), "r"(a[4 * j + 1]), "r"(a[4 * j + 2]),
                      "r"(a[4 * j + 3]), "r"(b0), "r"(b1));
            }
            const int c0 = kt + 8 * c + 2 * qd;
            const float e2a = se2[buf][8 * c + 2 * qd];
            const float e2b = se2[buf][8 * c + 2 * qd + 1];
            top3_update(__fmaf_rn(d0, -2.f, __fadd_rn(z2A, e2a)), c0,
                        s1A, i1A, s2A, i2A, s3A);
            top3_update(__fmaf_rn(d1, -2.f, __fadd_rn(z2A, e2b)), c0 + 1,
                        s1A, i1A, s2A, i2A, s3A);
            top3_update(__fmaf_rn(d2, -2.f, __fadd_rn(z2B, e2a)), c0,
                        s1B, i1B, s2B, i2B, s3B);
            top3_update(__fmaf_rn(d3, -2.f, __fadd_rn(z2B, e2b)), c0 + 1,
                        s1B, i1B, s2B, i2B, s3B);
        }

        __syncthreads();
        if (t + 2 < NTIL) {
            unsigned sb = (unsigned)__cvta_generic_to_shared(&se[buf][0]);
            const char* gb = (const char*)(g_embp + (size_t)(t + 2) * TKC * EP);
            for (int j = tid; j < TILE_CHUNKS; j += 128)
                cp_async16(sb + j * 16, gb + j * 16);
            if (tid < 16)
                cp_async16((unsigned)__cvta_generic_to_shared(&se2[buf][tid * 4]),
                           (const char*)(g_e2 + (t + 2) * TKC) + tid * 16);
            cp_commit();
        }
    }

    // Merge lanes (xor 1, xor 2 within each 4-lane group) → row top-3
    top3_merge(1, s1A, i1A, s2A, i2A, s3A);
    top3_merge(2, s1A, i1A, s2A, i2A, s3A);
    top3_merge(1, s1B, i1B, s2B, i2B, s3B);
    top3_merge(2, s1B, i1B, s2B, i2B, s3B);

    if (qd == 0) {
        emit_row(rowA, s1A, i1A, s2A, i2A, s3A, tauA);
        emit_row(rowB, s1B, i1B, s2B, i2B, s3B, tauB);
    }
}

// ---------------------------------------------------------------------------
// Kernel 4: fallback — exact frozen full scan for flagged rows (1 warp/row)
// ---------------------------------------------------------------------------
__global__ void __launch_bounds__(128) fb_kernel(const float* __restrict__ z,
                                                 const float* __restrict__ emb) {
    const int wg = blockIdx.x * 4 + (threadIdx.x >> 5);
    const int lane = threadIdx.x & 31;
    const unsigned cnt = g_fb_cnt;
    for (unsigned i = wg; i < cnt; i += FB_WARPS) {
        const int row = g_fb[i];
        const float* zp = z + (size_t)(row >> 14) * NC * SP + (row & (SP - 1));
        unsigned long long zr[NC / 2];
        const float z2 = load_row_frozen(zp, zr);
        float best = __int_as_float(0x7f800000);
        int bk = KCODES;
        for (int j = 0; j < 32; j++) {
            const int code = lane + 32 * j;
            const float s = frozen_score(zr, z2, emb, code);
            if (s < best || (s == best && code < bk)) { best = s; bk = code; }
        }
#pragma unroll
        for (int m = 16; m; m >>= 1) {
            float so = __shfl_xor_sync(0xffffffffu, best, m);
            int ko = __shfl_xor_sync(0xffffffffu, bk, m);
            if (so < best || (so == best && ko < bk)) { best = so; bk = ko; }
        }
        if (lane == 0) g_fbbk[row] = bk;
    }
}

// ---------------------------------------------------------------------------
// Kernel 5: resolve winner + STE epilogue + loss partials (1 row/thread)
// ---------------------------------------------------------------------------
__global__ void __launch_bounds__(128) epi_kernel(const float* __restrict__ z,
                                                  const float* __restrict__ emb,
                                                  float* __restrict__ out,
                                                  int write_idx) {
    __shared__ float wsum[4];
    const int tid = threadIdx.x;
    const int row = blockIdx.x * 128 + tid;
    const int b = row >> 14;
    const int s = row & (SP - 1);
    const float* zp = z + (size_t)b * NC * SP + s;

    const int2 cd = g_cand[row];
    int bk;
    if (cd.y == -2) bk = g_fbbk[row];
    else if (cd.y < 0) bk = cd.x;
    else {
        unsigned long long zr[NC / 2];
        const float z2 = load_row_frozen(zp, zr);
        const int ka = min(cd.x, cd.y), kb = max(cd.x, cd.y);
        const float sa = frozen_score(zr, z2, emb, ka);
        const float sb = frozen_score(zr, z2, emb, kb);
        bk = (sb < sa) ? kb : ka;     // strict <; tie → lower idx
    }

    const float4* eb4 = (const float4*)(emb + (size_t)bk * NC);
    float* oz = out + (size_t)b * NC * SP + s;
    float lsum = 0.f;
#pragma unroll
    for (int i = 0; i < NC / 4; i++) {
        float4 e = eb4[i];
        float zq0 = zp[(size_t)(4 * i + 0) * SP];
        float zq1 = zp[(size_t)(4 * i + 1) * SP];
        float zq2 = zp[(size_t)(4 * i + 2) * SP];
        float zq3 = zp[(size_t)(4 * i + 3) * SP];
        float q0 = __fadd_rn(zq0, __fsub_rn(e.x, zq0));
        float q1 = __fadd_rn(zq1, __fsub_rn(e.y, zq1));
        float q2 = __fadd_rn(zq2, __fsub_rn(e.z, zq2));
        float q3 = __fadd_rn(zq3, __fsub_rn(e.w, zq3));
        float d0 = __fsub_rn(q0, zq0);
        float d1 = __fsub_rn(q1, zq1);
        float d2 = __fsub_rn(q2, zq2);
        float d3 = __fsub_rn(q3, zq3);
        lsum += d0 * d0 + d1 * d1 + d2 * d2 + d3 * d3;
        oz[(size_t)(4 * i + 0) * SP] = q0;
        oz[(size_t)(4 * i + 1) * SP] = q1;
        oz[(size_t)(4 * i + 2) * SP] = q2;
        oz[(size_t)(4 * i + 3) * SP] = q3;
    }

    if (write_idx) out[(size_t)NZQ + 1 + row] = (float)bk;

    const int lane = tid & 31;
    const int wrp = tid >> 5;
#pragma unroll
    for (int off = 16; off; off >>= 1)
        lsum += __shfl_down_sync(0xffffffffu, lsum, off);
    if (lane == 0) wsum[wrp] = lsum;
    __syncthreads();
    if (tid == 0) {
        double sd = 0.0;
#pragma unroll
        for (int w = 0; w < 4; w++) sd += (double)wsum[w];
        g_partial[blockIdx.x] = sd;
    }
}

// ---------------------------------------------------------------------------
// Kernel 6: deterministic final loss reduction + fb-counter reset
// ---------------------------------------------------------------------------
__global__ void fin_kernel(float* __restrict__ out, int write_loss) {
    __shared__ double sd[256];
    int t = threadIdx.x;
    double s = 0.0;
#pragma unroll
    for (int i = 0; i < NBLK_EPI / 256; i++) s += g_partial[t + i * 256];
    sd[t] = s;
    __syncthreads();
    for (int st = 128; st >= 1; st >>= 1) {
        if (t < st) sd[t] += sd[t + st];
        __syncthreads();
    }
    if (t == 0) {
        if (write_loss)
            out[NZQ] = (float)(1.25 * sd[0] / (double)NZQ);
        g_fb_cnt = 0;   // reset for next graph replay
    }
}

// ---------------------------------------------------------------------------
extern "C" void kernel_launch(void* const* d_in, const int* in_sizes, int n_in,
                              void* d_out, int out_size) {
    const float* z = (const float*)d_in[0];
    const float* emb = (const float*)d_in[1];
    if (n_in >= 2 && in_sizes[0] == KCODES * NC && in_sizes[1] == NZQ) {
        const float* tmp = z; z = emb; emb = tmp;
    }
    float* out = (float*)d_out;
    const int write_loss = (out_size >= NZQ + 1) ? 1 : 0;
    const int write_idx = (out_size >= NZQ + 1 + NROWS) ? 1 : 0;

    prep_kernel<<<(KCODES + 127) / 128, 128>>>(emb);
    z2r_kernel<<<NROWS / 128, 128>>>(z);
    sweep_kernel<<<NROWS / 64, 128>>>(z);
    fb_kernel<<<FB_WARPS / 4, 128>>>(z, emb);
    epi_kernel<<<NBLK_EPI, 128>>>(z, emb, out, write_idx);
    fin_kernel<<<1, 256>>>(out, write_loss);
}

// round 15
// speedup vs baseline: 1.0656x; 1.0656x over previous
#include <cuda_runtime.h>
#include <mma.h>

using namespace nvcuda;

// Problem constants (z: (4,64,16,32,32) f32, emb: (1024,64) f32)
#define NBATCH 4
#define NC     64
#define SP     16384
#define NROWS  (NBATCH * SP)        // 65536
#define KCODES 1024
#define NZQ    (NBATCH * NC * SP)   // 4194304
#define EP     68                   // padded stride (floats), multiple of 4
#define TKC    32                   // codes per sweep smem tile
#define NTIL   (KCODES / TKC)       // 32
#define TCHUNK ((TKC * EP * 4) / 16)  // 544 x 16B
#define DLD    20                   // D scratch stride (multiple of 4!)
#define FTK    64                   // fallback tile codes
#define NBLK_EPI (NROWS / 128)      // 512

__device__ float    g_embp[KCODES * EP];   // tf32-rounded padded codebook
__device__ float    g_e2[KCODES];          // frozen code norms
__device__ float    g_z2[NROWS];           // frozen row norms
__device__ float    g_R[NROWS];            // sum |z| per row
__device__ unsigned g_maxe_bits;
__device__ int2     g_cand[NROWS];         // x=i1; y: -2 fb, -1 single, else i2
__device__ int      g_fb[NROWS];
__device__ int      g_fbbk[NROWS];
__device__ unsigned g_fb_cnt = 0;
__device__ double   g_partial[NBLK_EPI];

// ---------------------------------------------------------------------------
__device__ __forceinline__ void cp_async16(unsigned smem_addr, const void* gptr) {
    asm volatile("cp.async.cg.shared.global [%0], [%1], 16;\n"
                 :: "r"(smem_addr), "l"(gptr));
}
__device__ __forceinline__ void cp_commit() {
    asm volatile("cp.async.commit_group;\n");
}
template <int N>
__device__ __forceinline__ void cp_wait() {
    asm volatile("cp.async.wait_group %0;\n" :: "n"(N));
}

#define FMA2(acc, x, y) \
    asm("fma.rn.f32x2 %0, %1, %2, %0;" : "+l"(acc) : "l"(x), "l"(y))
#define ADD2(a, b) \
    asm("add.rn.f32x2 %0, %0, %1;" : "+l"(a) : "l"(b))

// Frozen row load: pairwise z2 tree + packed f32x2 (IDENTICAL to round-1)
__device__ __forceinline__ float load_row_frozen(const float* __restrict__ zp,
                                                 unsigned long long* zr) {
    float zv[NC];
#pragma unroll
    for (int c = 0; c < NC; c++) zv[c] = zp[(size_t)c * SP];
    float t32[32];
#pragma unroll
    for (int i = 0; i < 32; i++)
        t32[i] = __fadd_rn(__fmul_rn(zv[2 * i], zv[2 * i]),
                           __fmul_rn(zv[2 * i + 1], zv[2 * i + 1]));
#pragma unroll
    for (int st = 16; st >= 1; st >>= 1)
#pragma unroll
        for (int i = 0; i < 16; i++)
            if (i < st) t32[i] = __fadd_rn(t32[i], t32[i + st]);
#pragma unroll
    for (int j = 0; j < NC / 2; j++)
        asm("mov.b64 %0, {%1, %2};" : "=l"(zr[j]) : "f"(zv[2 * j]), "f"(zv[2 * j + 1]));
    return t32[0];
}

// Frozen exact dot chain (IDENTICAL to rounds 7-9) over an arbitrary e-row ptr
__device__ __forceinline__ float frozen_dot(const unsigned long long* zr,
                                            const float* erow) {
    const ulonglong2* ep = (const ulonglong2*)erow;
    unsigned long long a0 = 0ull, a1 = 0ull, a2 = 0ull, a3 = 0ull;
#pragma unroll
    for (int i = 0; i < 8; i++) {
        ulonglong2 e01 = ep[2 * i];
        ulonglong2 e23 = ep[2 * i + 1];
        FMA2(a0, zr[4 * i + 0], e01.x);
        FMA2(a1, zr[4 * i + 1], e01.y);
        FMA2(a2, zr[4 * i + 2], e23.x);
        FMA2(a3, zr[4 * i + 3], e23.y);
    }
    ADD2(a0, a1); ADD2(a2, a3); ADD2(a0, a2);
    float lo, hi;
    asm("mov.b64 {%0, %1}, %2;" : "=f"(lo), "=f"(hi) : "l"(a0));
    return __fadd_rn(lo, hi);
}

__device__ __forceinline__ float frozen_score_g(const unsigned long long* zr,
                                                float z2,
                                                const float* __restrict__ emb,
                                                int code) {
    const float dot = frozen_dot(zr, emb + (size_t)code * NC);
    return __fmaf_rn(dot, -2.0f, __fadd_rn(z2, g_e2[code]));
}

// ---------------------------------------------------------------------------
// Kernel 1: frozen e2, tf32 padded codebook, max|e|
// ---------------------------------------------------------------------------
__global__ void prep_kernel(const float* __restrict__ emb) {
    int k = blockIdx.x * blockDim.x + threadIdx.x;
    if (k < KCODES) {
        const float4* e = (const float4*)(emb + k * NC);
        float s = 0.f, mx = 0.f;
#pragma unroll
        for (int i = 0; i < NC / 4; i++) {
            float4 v = e[i];
            s += v.x * v.x + v.y * v.y + v.z * v.z + v.w * v.w;
            mx = fmaxf(mx, fmaxf(fmaxf(fabsf(v.x), fabsf(v.y)),
                                 fmaxf(fabsf(v.z), fabsf(v.w))));
            unsigned t0, t1, t2, t3;
            asm("cvt.rna.tf32.f32 %0, %1;" : "=r"(t0) : "f"(v.x));
            asm("cvt.rna.tf32.f32 %0, %1;" : "=r"(t1) : "f"(v.y));
            asm("cvt.rna.tf32.f32 %0, %1;" : "=r"(t2) : "f"(v.z));
            asm("cvt.rna.tf32.f32 %0, %1;" : "=r"(t3) : "f"(v.w));
            g_embp[k * EP + 4 * i + 0] = __uint_as_float(t0);
            g_embp[k * EP + 4 * i + 1] = __uint_as_float(t1);
            g_embp[k * EP + 4 * i + 2] = __uint_as_float(t2);
            g_embp[k * EP + 4 * i + 3] = __uint_as_float(t3);
        }
        g_e2[k] = s;
        atomicMax(&g_maxe_bits, __float_as_uint(mx));
    }
}

// ---------------------------------------------------------------------------
// Kernel 2: frozen z2 + R per row
// ---------------------------------------------------------------------------
__global__ void __launch_bounds__(128) z2r_kernel(const float* __restrict__ z) {
    const int row = blockIdx.x * 128 + threadIdx.x;
    const float* zp = z + (size_t)(row >> 14) * NC * SP + (row & (SP - 1));
    float zv[NC];
#pragma unroll
    for (int c = 0; c < NC; c++) zv[c] = zp[(size_t)c * SP];
    float t32[32];
#pragma unroll
    for (int i = 0; i < 32; i++)
        t32[i] = __fadd_rn(__fmul_rn(zv[2 * i], zv[2 * i]),
                           __fmul_rn(zv[2 * i + 1], zv[2 * i + 1]));
#pragma unroll
    for (int st = 16; st >= 1; st >>= 1)
#pragma unroll
        for (int i = 0; i < 16; i++)
            if (i < st) t32[i] = __fadd_rn(t32[i], t32[i + st]);
    float R = 0.f;
#pragma unroll
    for (int c = 0; c < NC; c++) R += fabsf(zv[c]);
    g_z2[row] = t32[0];
    g_R[row] = R;
}

// ---------------------------------------------------------------------------
// top-3 helpers
// ---------------------------------------------------------------------------
__device__ __forceinline__ void top3_update(float s, int idx, float& s1, int& i1,
                                            float& s2, int& i2, float& s3) {
    if (s < s3) {
        if (s < s2) {
            s3 = s2;
            if (s < s1) { s2 = s1; i2 = i1; s1 = s; i1 = idx; }
            else        { s2 = s;  i2 = idx; }
        } else s3 = s;
    }
}

__device__ __forceinline__ void top3_merge(int m, float& s1, int& i1,
                                           float& s2, int& i2, float& s3) {
    float b1 = __shfl_xor_sync(0xffffffffu, s1, m);
    float b2 = __shfl_xor_sync(0xffffffffu, s2, m);
    float b3 = __shfl_xor_sync(0xffffffffu, s3, m);
    int  j1 = __shfl_xor_sync(0xffffffffu, i1, m);
    int  j2 = __shfl_xor_sync(0xffffffffu, i2, m);
    float n1, n2, n3; int k1, k2;
    if (s1 <= b1) {
        n1 = s1; k1 = i1;
        if (s2 <= b1) { n2 = s2; k2 = i2; n3 = fminf(s3, b1); }
        else          { n2 = b1; k2 = j1; n3 = fminf(s2, b2); }
    } else {
        n1 = b1; k1 = j1;
        if (b2 <= s1) { n2 = b2; k2 = j2; n3 = fminf(b3, s1); }
        else          { n2 = s1; k2 = i1; n3 = fminf(b2, s2); }
    }
    s1 = n1; i1 = k1; s2 = n2; i2 = k2; s3 = n3;
}

// ---------------------------------------------------------------------------
// Kernel 3: WMMA tf32 filter. Block = 128 thr (4 warps) = 64 rows.
// D stored to smem row-major with LEGAL ldm (DLD=20, multiple of 4).
// ---------------------------------------------------------------------------
__global__ void __launch_bounds__(128) sweep_kernel(const float* __restrict__ z) {
    __shared__ __align__(32) float sa[64 * EP];        // A: 64 rows tf32
    __shared__ __align__(32) float sb[2][TKC * EP];    // B tiles
    __shared__ __align__(32) float se2[2][TKC];
    __shared__ __align__(32) float sd[4][16 * DLD];    // per-warp D scratch

    const int tid = threadIdx.x;
    const int warp = tid >> 5;
    const int lane = tid & 31;
    const int mrow = lane & 15;
    const int half = lane >> 4;

    const int blockRow = blockIdx.x * 64;
    const int batch = blockRow >> 14;
    const int s0 = blockRow & (SP - 1);
    const float* zbase = z + (size_t)batch * NC * SP;

    // Prime B tiles 0,1 + e2
#pragma unroll
    for (int t = 0; t < 2; t++) {
        unsigned sbb = (unsigned)__cvta_generic_to_shared(&sb[t][0]);
        const char* gb = (const char*)(g_embp + (size_t)t * TKC * EP);
        for (int j = tid; j < TCHUNK; j += 128)
            cp_async16(sbb + j * 16, gb + j * 16);
        if (tid < TKC / 4)
            cp_async16((unsigned)__cvta_generic_to_shared(&se2[t][tid * 4]),
                       (const char*)(g_e2 + t * TKC) + tid * 16);
        cp_commit();
    }

    // Stage A (tf32-rounded) to smem: sa[row][chan], coalesced gmem reads
    for (int i = tid; i < 64 * 64; i += 128) {
        const int c = i >> 6;
        const int r = i & 63;
        float v = zbase[(size_t)c * SP + s0 + r];
        unsigned tv;
        asm("cvt.rna.tf32.f32 %0, %1;" : "=r"(tv) : "f"(v));
        sa[r * EP + c] = __uint_as_float(tv);
    }
    __syncthreads();

    const int rowIdx = blockRow + warp * 16 + mrow;
    const float z2 = g_z2[rowIdx];
    const float maxe = __uint_as_float(g_maxe_bits);
    const float tau = __fmaf_rn(g_R[rowIdx] * maxe, 0.0078125f, 3e-4f);

    const float INF = __int_as_float(0x7f800000);
    float s1 = INF, s2 = INF, s3 = INF;
    int i1 = 0, i2 = 0;

    for (int t = 0; t < NTIL; t++) {
        if (t < NTIL - 1) cp_wait<1>(); else cp_wait<0>();
        __syncthreads();
        const int buf = t & 1;
        const int kt = t * TKC;

#pragma unroll
        for (int cb = 0; cb < TKC; cb += 16) {
            wmma::fragment<wmma::accumulator, 16, 16, 8, float> acc;
            wmma::fill_fragment(acc, 0.0f);
#pragma unroll
            for (int kk = 0; kk < 8; kk++) {
                wmma::fragment<wmma::matrix_a, 16, 16, 8,
                               wmma::precision::tf32, wmma::row_major> af;
                wmma::fragment<wmma::matrix_b, 16, 16, 8,
                               wmma::precision::tf32, wmma::col_major> bf;
                wmma::load_matrix_sync(af, &sa[(warp * 16) * EP + kk * 8], EP);
                wmma::load_matrix_sync(bf, &sb[buf][cb * EP + kk * 8], EP);
                wmma::mma_sync(acc, af, bf, acc);
            }
            wmma::store_matrix_sync(&sd[warp][0], acc, DLD, wmma::mem_row_major);
            __syncwarp();
            // scan D with EXPLICIT indices: sd[m][n] = dot(row m, code kt+cb+n)
#pragma unroll
            for (int n0 = 0; n0 < 8; n0++) {
                const int n = half * 8 + n0;
                const int code = kt + cb + n;
                const float d = sd[warp][mrow * DLD + n];
                const float s = __fmaf_rn(d, -2.0f,
                                          __fadd_rn(z2, se2[buf][cb + n]));
                top3_update(s, code, s1, i1, s2, i2, s3);
            }
            __syncwarp();
        }

        __syncthreads();
        if (t + 2 < NTIL) {
            unsigned sbb = (unsigned)__cvta_generic_to_shared(&sb[buf][0]);
            const char* gb = (const char*)(g_embp + (size_t)(t + 2) * TKC * EP);
            for (int j = tid; j < TCHUNK; j += 128)
                cp_async16(sbb + j * 16, gb + j * 16);
            if (tid < TKC / 4)
                cp_async16((unsigned)__cvta_generic_to_shared(&se2[buf][tid * 4]),
                           (const char*)(g_e2 + (t + 2) * TKC) + tid * 16);
            cp_commit();
        }
    }

    // merge the two half-lanes of each row
    top3_merge(16, s1, i1, s2, i2, s3);

    if (lane < 16) {
        int y;
        if (!(s3 > s1 + tau)) {                 // NaN-safe: NaN -> fallback
            y = -2;
            unsigned p = atomicAdd(&g_fb_cnt, 1u);
            g_fb[p] = rowIdx;
        } else if (!(s2 > s1 + tau)) y = i2;
        else y = -1;
        g_cand[rowIdx] = make_int2(i1, y);
    }
}

// ---------------------------------------------------------------------------
// Kernel 4: compacted exact fallback — 128 flagged rows/block, smem code
// tiles, frozen numerics. Blocks beyond the flagged count exit immediately.
// ---------------------------------------------------------------------------
__global__ void __launch_bounds__(128) fb_kernel(const float* __restrict__ z,
                                                 const float* __restrict__ emb) {
    __shared__ __align__(16) float se[2][FTK * NC];   // 2 x 16 KB
    __shared__ __align__(16) float fe2[2][FTK];

    const int cnt = (int)g_fb_cnt;
    const int base = blockIdx.x * 128;
    if (base >= cnt) return;
    const int tid = threadIdx.x;
    const int li = base + tid;
    const int row = g_fb[li < cnt ? li : cnt - 1];

    // Prime tiles 0,1 (+e2)
#pragma unroll
    for (int t = 0; t < 2; t++) {
        unsigned sbb = (unsigned)__cvta_generic_to_shared(&se[t][0]);
        const char* gb = (const char*)(emb + (size_t)t * FTK * NC);
#pragma unroll
        for (int j = 0; j < (FTK * NC * 4) / (128 * 16); j++)
            cp_async16(sbb + (tid + j * 128) * 16, gb + (tid + j * 128) * 16);
        if (tid < FTK / 4)
            cp_async16((unsigned)__cvta_generic_to_shared(&fe2[t][tid * 4]),
                       (const char*)(g_e2 + t * FTK) + tid * 16);
        cp_commit();
    }

    const float* zp = z + (size_t)(row >> 14) * NC * SP + (row & (SP - 1));
    unsigned long long zr[NC / 2];
    const float z2 = load_row_frozen(zp, zr);

    float best = __int_as_float(0x7f800000);
    int bk = 0;

    for (int t = 0; t < KCODES / FTK; t++) {
        if (t < KCODES / FTK - 1) cp_wait<1>(); else cp_wait<0>();
        __syncthreads();
        const int buf = t & 1;
        const int k0 = t * FTK;

        for (int kk = 0; kk < FTK; kk++) {
            const float dot = frozen_dot(zr, &se[buf][kk * NC]);
            const float sc = __fmaf_rn(dot, -2.0f, __fadd_rn(z2, fe2[buf][kk]));
            if (sc < best) { best = sc; bk = k0 + kk; }
        }

        __syncthreads();
        if (t + 2 < KCODES / FTK) {
            unsigned sbb = (unsigned)__cvta_generic_to_shared(&se[buf][0]);
            const char* gb = (const char*)(emb + (size_t)(t + 2) * FTK * NC);
#pragma unroll
            for (int j = 0; j < (FTK * NC * 4) / (128 * 16); j++)
                cp_async16(sbb + (tid + j * 128) * 16, gb + (tid + j * 128) * 16);
            if (tid < FTK / 4)
                cp_async16((unsigned)__cvta_generic_to_shared(&fe2[buf][tid * 4]),
                           (const char*)(g_e2 + (t + 2) * FTK) + tid * 16);
            cp_commit();
        }
    }

    if (li < cnt) g_fbbk[row] = bk;
}

// ---------------------------------------------------------------------------
// Kernel 5: resolve winner + STE epilogue + loss partials (1 row/thread)
// ---------------------------------------------------------------------------
__global__ void __launch_bounds__(128) epi_kernel(const float* __restrict__ z,
                                                  const float* __restrict__ emb,
                                                  float* __restrict__ out,
                                                  int write_idx) {
    __shared__ float wsum[4];
    const int tid = threadIdx.x;
    const int row = blockIdx.x * 128 + tid;
    const int b = row >> 14;
    const int s = row & (SP - 1);
    const float* zp = z + (size_t)b * NC * SP + s;

    const int2 cd = g_cand[row];
    int bk;
    if (cd.y == -2) bk = g_fbbk[row];
    else if (cd.y < 0) bk = cd.x;
    else {
        unsigned long long zr[NC / 2];
        const float z2 = load_row_frozen(zp, zr);
        const int ka = min(cd.x, cd.y), kb = max(cd.x, cd.y);
        const float sa = frozen_score_g(zr, z2, emb, ka);
        const float sb = frozen_score_g(zr, z2, emb, kb);
        bk = (sb < sa) ? kb : ka;     // strict <; tie -> lower idx
    }

    const float4* eb4 = (const float4*)(emb + (size_t)bk * NC);
    float* oz = out + (size_t)b * NC * SP + s;
    float lsum = 0.f;
#pragma unroll
    for (int i = 0; i < NC / 4; i++) {
        float4 e = eb4[i];
        float zq0 = zp[(size_t)(4 * i + 0) * SP];
        float zq1 = zp[(size_t)(4 * i + 1) * SP];
        float zq2 = zp[(size_t)(4 * i + 2) * SP];
        float zq3 = zp[(size_t)(4 * i + 3) * SP];
        float q0 = __fadd_rn(zq0, __fsub_rn(e.x, zq0));
        float q1 = __fadd_rn(zq1, __fsub_rn(e.y, zq1));
        float q2 = __fadd_rn(zq2, __fsub_rn(e.z, zq2));
        float q3 = __fadd_rn(zq3, __fsub_rn(e.w, zq3));
        float d0 = __fsub_rn(q0, zq0);
        float d1 = __fsub_rn(q1, zq1);
        float d2 = __fsub_rn(q2, zq2);
        float d3 = __fsub_rn(q3, zq3);
        lsum += d0 * d0 + d1 * d1 + d2 * d2 + d3 * d3;
        oz[(size_t)(4 * i + 0) * SP] = q0;
        oz[(size_t)(4 * i + 1) * SP] = q1;
        oz[(size_t)(4 * i + 2) * SP] = q2;
        oz[(size_t)(4 * i + 3) * SP] = q3;
    }

    if (write_idx) out[(size_t)NZQ + 1 + row] = (float)bk;

    const int lane = tid & 31;
    const int wrp = tid >> 5;
#pragma unroll
    for (int off = 16; off; off >>= 1)
        lsum += __shfl_down_sync(0xffffffffu, lsum, off);
    if (lane == 0) wsum[wrp] = lsum;
    __syncthreads();
    if (tid == 0) {
        double sd = 0.0;
#pragma unroll
        for (int w = 0; w < 4; w++) sd += (double)wsum[w];
        g_partial[blockIdx.x] = sd;
    }
}

// ---------------------------------------------------------------------------
// Kernel 6: deterministic final loss reduction + fb-counter reset
// ---------------------------------------------------------------------------
__global__ void fin_kernel(float* __restrict__ out, int write_loss) {
    __shared__ double sd[256];
    int t = threadIdx.x;
    double s = 0.0;
#pragma unroll
    for (int i = 0; i < NBLK_EPI / 256; i++) s += g_partial[t + i * 256];
    sd[t] = s;
    __syncthreads();
    for (int st = 128; st >= 1; st >>= 1) {
        if (t < st) sd[t] += sd[t + st];
        __syncthreads();
    }
    if (t == 0) {
        if (write_loss)
            out[NZQ] = (float)(1.25 * sd[0] / (double)NZQ);
        g_fb_cnt = 0;   // reset for next graph replay
    }
}

// ---------------------------------------------------------------------------
extern "C" void kernel_launch(void* const* d_in, const int* in_sizes, int n_in,
                              void* d_out, int out_size) {
    const float* z = (const float*)d_in[0];
    const float* emb = (const float*)d_in[1];
    if (n_in >= 2 && in_sizes[0] == KCODES * NC && in_sizes[1] == NZQ) {
        const float* tmp = z; z = emb; emb = tmp;
    }
    float* out = (float*)d_out;
    const int write_loss = (out_size >= NZQ + 1) ? 1 : 0;
    const int write_idx = (out_size >= NZQ + 1 + NROWS) ? 1 : 0;

    prep_kernel<<<(KCODES + 127) / 128, 128>>>(emb);
    z2r_kernel<<<NROWS / 128, 128>>>(z);
    sweep_kernel<<<NROWS / 64, 128>>>(z);
    fb_kernel<<<NROWS / 128, 128>>>(z, emb);
    epi_kernel<<<NBLK_EPI, 128>>>(z, emb, out, write_idx);
    fin_kernel<<<1, 256>>>(out, write_loss);
}

// round 17
// speedup vs baseline: 1.2544x; 1.1771x over previous
#include <cuda_runtime.h>

// Problem constants (z: (4,64,16,32,32) f32, emb: (1024,64) f32)
#define NBATCH 4
#define NC     64
#define SP     16384
#define NROWS  (NBATCH * SP)        // 65536
#define KCODES 1024
#define NZQ    (NBATCH * NC * SP)   // 4194304
#define FTK    64                   // codes per smem tile
#define NTILF  (KCODES / FTK)       // 16
#define NBLK   (NROWS / 128)        // 512

__device__ float  g_e2[KCODES];     // frozen code norms
__device__ int    g_bk[NROWS];      // winning code per row
__device__ double g_partial[NBLK];

// ---------------------------------------------------------------------------
__device__ __forceinline__ void cp_async16(unsigned smem_addr, const void* gptr) {
    asm volatile("cp.async.cg.shared.global [%0], [%1], 16;\n"
                 :: "r"(smem_addr), "l"(gptr));
}
__device__ __forceinline__ void cp_commit() {
    asm volatile("cp.async.commit_group;\n");
}
template <int N>
__device__ __forceinline__ void cp_wait() {
    asm volatile("cp.async.wait_group %0;\n" :: "n"(N));
}

#define FMA2(acc, x, y) \
    asm("fma.rn.f32x2 %0, %1, %2, %0;" : "+l"(acc) : "l"(x), "l"(y))
#define ADD2(a, b) \
    asm("add.rn.f32x2 %0, %0, %1;" : "+l"(a) : "l"(b))

// Frozen row load: pairwise z2 tree + packed f32x2 (IDENTICAL to round-1,
// validated rel_err=0.0 through round 15)
__device__ __forceinline__ float load_row_frozen(const float* __restrict__ zp,
                                                 unsigned long long* zr) {
    float zv[NC];
#pragma unroll
    for (int c = 0; c < NC; c++) zv[c] = zp[(size_t)c * SP];
    float t32[32];
#pragma unroll
    for (int i = 0; i < 32; i++)
        t32[i] = __fadd_rn(__fmul_rn(zv[2 * i], zv[2 * i]),
                           __fmul_rn(zv[2 * i + 1], zv[2 * i + 1]));
#pragma unroll
    for (int st = 16; st >= 1; st >>= 1)
#pragma unroll
        for (int i = 0; i < 16; i++)
            if (i < st) t32[i] = __fadd_rn(t32[i], t32[i + st]);
#pragma unroll
    for (int j = 0; j < NC / 2; j++)
        asm("mov.b64 %0, {%1, %2};" : "=l"(zr[j]) : "f"(zv[2 * j]), "f"(zv[2 * j + 1]));
    return t32[0];
}

// Frozen exact dot chain (IDENTICAL to rounds 7-15) over an smem e-row
__device__ __forceinline__ float frozen_dot(const unsigned long long* zr,
                                            const float* erow) {
    const ulonglong2* ep = (const ulonglong2*)erow;
    unsigned long long a0 = 0ull, a1 = 0ull, a2 = 0ull, a3 = 0ull;
#pragma unroll
    for (int i = 0; i < 8; i++) {
        ulonglong2 e01 = ep[2 * i];
        ulonglong2 e23 = ep[2 * i + 1];
        FMA2(a0, zr[4 * i + 0], e01.x);
        FMA2(a1, zr[4 * i + 1], e01.y);
        FMA2(a2, zr[4 * i + 2], e23.x);
        FMA2(a3, zr[4 * i + 3], e23.y);
    }
    ADD2(a0, a1); ADD2(a2, a3); ADD2(a0, a2);
    float lo, hi;
    asm("mov.b64 {%0, %1}, %2;" : "=f"(lo), "=f"(hi) : "l"(a0));
    return __fadd_rn(lo, hi);
}

// ---------------------------------------------------------------------------
// Kernel 1: frozen per-code squared norms (validated contraction)
// ---------------------------------------------------------------------------
__global__ void prep_kernel(const float* __restrict__ emb) {
    int k = blockIdx.x * blockDim.x + threadIdx.x;
    if (k < KCODES) {
        const float4* e = (const float4*)(emb + k * NC);
        float s = 0.f;
#pragma unroll
        for (int i = 0; i < NC / 4; i++) {
            float4 v = e[i];
            s += v.x * v.x + v.y * v.y + v.z * v.z + v.w * v.w;
        }
        g_e2[k] = s;
    }
}

// ---------------------------------------------------------------------------
// Kernel 2: full exact scan — the round-15 fb_kernel architecture (measured
// 134us covering ~all rows), with DIRECT row mapping (coalesced z loads)
// and no queue indirection. 1 row/thread, 1024 codes from smem tiles,
// frozen numerics, ascending-k strict-< first-min.
// ---------------------------------------------------------------------------
__global__ void __launch_bounds__(128) scan_kernel(const float* __restrict__ z,
                                                   const float* __restrict__ emb) {
    __shared__ __align__(16) float se[2][FTK * NC];   // 2 x 16 KB code tiles
    __shared__ __align__(16) float fe2[2][FTK];

    const int tid = threadIdx.x;
    const int row = blockIdx.x * 128 + tid;

    // Prime tiles 0,1 (+e2)
#pragma unroll
    for (int t = 0; t < 2; t++) {
        unsigned sbb = (unsigned)__cvta_generic_to_shared(&se[t][0]);
        const char* gb = (const char*)(emb + (size_t)t * FTK * NC);
#pragma unroll
        for (int j = 0; j < (FTK * NC * 4) / (128 * 16); j++)
            cp_async16(sbb + (tid + j * 128) * 16, gb + (tid + j * 128) * 16);
        if (tid < FTK / 4)
            cp_async16((unsigned)__cvta_generic_to_shared(&fe2[t][tid * 4]),
                       (const char*)(g_e2 + t * FTK) + tid * 16);
        cp_commit();
    }

    const float* zp = z + (size_t)(row >> 14) * NC * SP + (row & (SP - 1));
    unsigned long long zr[NC / 2];
    const float z2 = load_row_frozen(zp, zr);

    float best = __int_as_float(0x7f800000);
    int bk = 0;

    for (int t = 0; t < NTILF; t++) {
        if (t < NTILF - 1) cp_wait<1>(); else cp_wait<0>();
        __syncthreads();
        const int buf = t & 1;
        const int k0 = t * FTK;

        for (int kk = 0; kk < FTK; kk++) {
            const float dot = frozen_dot(zr, &se[buf][kk * NC]);
            const float sc = __fmaf_rn(dot, -2.0f, __fadd_rn(z2, fe2[buf][kk]));
            if (sc < best) { best = sc; bk = k0 + kk; }
        }

        __syncthreads();
        if (t + 2 < NTILF) {
            unsigned sbb = (unsigned)__cvta_generic_to_shared(&se[buf][0]);
            const char* gb = (const char*)(emb + (size_t)(t + 2) * FTK * NC);
#pragma unroll
            for (int j = 0; j < (FTK * NC * 4) / (128 * 16); j++)
                cp_async16(sbb + (tid + j * 128) * 16, gb + (tid + j * 128) * 16);
            if (tid < FTK / 4)
                cp_async16((unsigned)__cvta_generic_to_shared(&fe2[buf][tid * 4]),
                           (const char*)(g_e2 + (t + 2) * FTK) + tid * 16);
            cp_commit();
        }
    }

    g_bk[row] = bk;
}

// ---------------------------------------------------------------------------
// Kernel 3: STE epilogue + loss partials (1 row/thread; validated numerics)
// ---------------------------------------------------------------------------
__global__ void __launch_bounds__(128) epi_kernel(const float* __restrict__ z,
                                                  const float* __restrict__ emb,
                                                  float* __restrict__ out,
                                                  int write_idx) {
    __shared__ float wsum[4];
    const int tid = threadIdx.x;
    const int row = blockIdx.x * 128 + tid;
    const int b = row >> 14;
    const int s = row & (SP - 1);
    const float* zp = z + (size_t)b * NC * SP + s;

    const int bk = g_bk[row];

    const float4* eb4 = (const float4*)(emb + (size_t)bk * NC);
    float* oz = out + (size_t)b * NC * SP + s;
    float lsum = 0.f;
#pragma unroll
    for (int i = 0; i < NC / 4; i++) {
        float4 e = eb4[i];
        float zq0 = zp[(size_t)(4 * i + 0) * SP];
        float zq1 = zp[(size_t)(4 * i + 1) * SP];
        float zq2 = zp[(size_t)(4 * i + 2) * SP];
        float zq3 = zp[(size_t)(4 * i + 3) * SP];
        // Frozen STE numerics: q = zc + (e - zc)
        float q0 = __fadd_rn(zq0, __fsub_rn(e.x, zq0));
        float q1 = __fadd_rn(zq1, __fsub_rn(e.y, zq1));
        float q2 = __fadd_rn(zq2, __fsub_rn(e.z, zq2));
        float q3 = __fadd_rn(zq3, __fsub_rn(e.w, zq3));
        float d0 = __fsub_rn(q0, zq0);
        float d1 = __fsub_rn(q1, zq1);
        float d2 = __fsub_rn(q2, zq2);
        float d3 = __fsub_rn(q3, zq3);
        lsum += d0 * d0 + d1 * d1 + d2 * d2 + d3 * d3;
        oz[(size_t)(4 * i + 0) * SP] = q0;
        oz[(size_t)(4 * i + 1) * SP] = q1;
        oz[(size_t)(4 * i + 2) * SP] = q2;
        oz[(size_t)(4 * i + 3) * SP] = q3;
    }

    if (write_idx) out[(size_t)NZQ + 1 + row] = (float)bk;

    const int lane = tid & 31;
    const int wrp = tid >> 5;
#pragma unroll
    for (int off = 16; off; off >>= 1)
        lsum += __shfl_down_sync(0xffffffffu, lsum, off);
    if (lane == 0) wsum[wrp] = lsum;
    __syncthreads();
    if (tid == 0) {
        double sd = 0.0;
#pragma unroll
        for (int w = 0; w < 4; w++) sd += (double)wsum[w];
        g_partial[blockIdx.x] = sd;
    }
}

// ---------------------------------------------------------------------------
// Kernel 4: deterministic final loss reduction
// ---------------------------------------------------------------------------
__global__ void fin_kernel(float* __restrict__ out, int write_loss) {
    __shared__ double sd[256];
    int t = threadIdx.x;
    double s = 0.0;
#pragma unroll
    for (int i = 0; i < NBLK / 256; i++) s += g_partial[t + i * 256];
    sd[t] = s;
    __syncthreads();
    for (int st = 128; st >= 1; st >>= 1) {
        if (t < st) sd[t] += sd[t + st];
        __syncthreads();
    }
    if (t == 0 && write_loss) {
        // vq_loss = mean(d^2) + 0.25*mean(d^2) = 1.25 * sum / NZQ
        out[NZQ] = (float)(1.25 * sd[0] / (double)NZQ);
    }
}

// ---------------------------------------------------------------------------
extern "C" void kernel_launch(void* const* d_in, const int* in_sizes, int n_in,
                              void* d_out, int out_size) {
    const float* z = (const float*)d_in[0];
    const float* emb = (const float*)d_in[1];
    // Defensive: identify tensors by element count (z: 4194304, emb: 65536)
    if (n_in >= 2 && in_sizes[0] == KCODES * NC && in_sizes[1] == NZQ) {
        const float* tmp = z; z = emb; emb = tmp;
    }
    float* out = (float*)d_out;
    const int write_loss = (out_size >= NZQ + 1) ? 1 : 0;
    const int write_idx = (out_size >= NZQ + 1 + NROWS) ? 1 : 0;

    prep_kernel<<<(KCODES + 127) / 128, 128>>>(emb);
    scan_kernel<<<NBLK, 128>>>(z, emb);
    epi_kernel<<<NBLK, 128>>>(z, emb, out, write_idx);
    fin_kernel<<<1, 256>>>(out, write_loss);
}